// round 5
// baseline (speedup 1.0000x reference)
#include <cuda_runtime.h>

#define VOCAB 10000
#define EMB   16
#define HID   32
#define NCLS  2
#define BATCH 4096
#define SEQ   512

typedef unsigned long long ull;

// Projected embedding table: proj[t][h] = sum_e emb[t][e]*W_ih[h][e] + b_ih[h] + b_hh[h]
__device__ float g_proj[VOCAB * HID];

__global__ void build_proj_kernel(const float* __restrict__ emb,
                                  const float* __restrict__ W_ih,
                                  const float* __restrict__ b_ih,
                                  const float* __restrict__ b_hh) {
    int t    = blockIdx.x * (blockDim.x >> 5) + (threadIdx.x >> 5);
    int lane = threadIdx.x & 31;
    if (t >= VOCAB) return;
    float acc = __ldg(b_ih + lane) + __ldg(b_hh + lane);
#pragma unroll
    for (int e = 0; e < EMB; e++) {
        acc = fmaf(__ldg(emb + t * EMB + e), __ldg(W_ih + lane * EMB + e), acc);
    }
    g_proj[t * HID + lane] = acc;
}

// tanh(x) = 1 - 2/(e^{2x}+1), branch-free via MUFU ex2/rcp. abs err ~1e-6.
__device__ __forceinline__ float fast_tanh(float x) {
    float e;
    asm("ex2.approx.f32 %0, %1;" : "=f"(e) : "f"(x * 2.8853900817779268f));
    float r;
    asm("rcp.approx.f32 %0, %1;" : "=f"(r) : "f"(e + 1.0f));
    return fmaf(-2.0f, r, 1.0f);
}

__device__ __forceinline__ ull pack2(float lo, float hi) {
    ull u;
    asm("mov.b64 %0, {%1, %2};" : "=l"(u) : "f"(lo), "f"(hi));
    return u;
}
__device__ __forceinline__ void unpack2(ull u, float& lo, float& hi) {
    asm("mov.b64 {%0, %1}, %2;" : "=f"(lo), "=f"(hi) : "l"(u));
}
__device__ __forceinline__ ull fma2(ull a, ull b, ull c) {
    asm("fma.rn.f32x2 %0, %1, %2, %3;" : "=l"(c) : "l"(a), "l"(b), "l"(c));
    return c;
}
__device__ __forceinline__ ull add2(ull a, ull b) {
    ull c;
    asm("add.rn.f32x2 %0, %1, %2;" : "=l"(c) : "l"(a), "l"(b));
    return c;
}
// 128-bit shared load -> two packed f32x2 operands (volatile: addresses repeat).
__device__ __forceinline__ void lds2(ull& a, ull& b, unsigned addr) {
    asm volatile("ld.shared.v2.u64 {%0, %1}, [%2];" : "=l"(a), "=l"(b) : "r"(addr));
}

// One warp per TWO sequences; lane = hidden unit (same W_hh row reused for both).
// Two independent recurrence chains per warp double the hideable ILP.
__global__ void __launch_bounds__(128) rnn_step_kernel(
    const int* __restrict__ x,
    const float* __restrict__ W_hh,
    const float* __restrict__ W_fc,
    const float* __restrict__ b_fc,
    float* __restrict__ out) {

    int wl   = threadIdx.x >> 5;
    int lane = threadIdx.x & 31;
    int base = (blockIdx.x * 4 + wl) * 2;          // seq A = base, seq B = base+1

    __shared__ __align__(16) float hbuf[4][2][2][HID];   // [warp][buf][seq][unit]

    // W_hh row for this lane, packed into 16 f32x2 registers (shared by both seqs).
    ull w2[HID / 2];
#pragma unroll
    for (int j = 0; j < HID / 2; j++) {
        float2 wf = __ldg((const float2*)(W_hh + lane * HID) + j);
        w2[j] = pack2(wf.x, wf.y);
    }

    unsigned bA0 = (unsigned)__cvta_generic_to_shared(&hbuf[wl][0][0][0]);
    unsigned bB0 = (unsigned)__cvta_generic_to_shared(&hbuf[wl][0][1][0]);
    unsigned bA1 = (unsigned)__cvta_generic_to_shared(&hbuf[wl][1][0][0]);
    unsigned bB1 = (unsigned)__cvta_generic_to_shared(&hbuf[wl][1][1][0]);

    const int4* xbA = (const int4*)(x + (base + 0) * SEQ);
    const int4* xbB = (const int4*)(x + (base + 1) * SEQ);

    hbuf[wl][0][0][lane] = 0.0f;
    hbuf[wl][0][1][lane] = 0.0f;
    float hA = 0.0f, hB = 0.0f;

    // Prime 2-deep proj prefetch for both sequences.
    int4 tA = __ldg(xbA);
    int4 tB = __ldg(xbB);
    float xpA0 = __ldg(&g_proj[tA.x * HID + lane]);
    float xpA1 = __ldg(&g_proj[tA.y * HID + lane]);
    float xpB0 = __ldg(&g_proj[tB.x * HID + lane]);
    float xpB1 = __ldg(&g_proj[tB.y * HID + lane]);

#define STEP(PAR, XPA, XPB, TPA, TPB)                                          \
    {                                                                          \
        float xuA = (XPA), xuB = (XPB);                                        \
        (XPA) = __ldg(&g_proj[(TPA) * HID + lane]); /* prefetch s+2 */         \
        (XPB) = __ldg(&g_proj[(TPB) * HID + lane]);                            \
        __syncwarp();                                                          \
        unsigned sA = (PAR) ? bA1 : bA0;                                       \
        unsigned sB = (PAR) ? bB1 : bB0;                                       \
        ull q0,q1,q2,q3,q4,q5,q6,q7, r0,r1,r2,r3,r4,r5,r6,r7;                  \
        ull aA0=0,aA1=0,aA2=0,aA3=0, aB0=0,aB1=0,aB2=0,aB3=0;                  \
        lds2(q0,q1,sA     ); lds2(r0,r1,sB     );                              \
        lds2(q2,q3,sA + 16); lds2(r2,r3,sB + 16);                              \
        lds2(q4,q5,sA + 32); lds2(r4,r5,sB + 32);                              \
        lds2(q6,q7,sA + 48); lds2(r6,r7,sB + 48);                              \
        aA0=fma2(q0,w2[0],aA0); aB0=fma2(r0,w2[0],aB0);                        \
        aA1=fma2(q1,w2[1],aA1); aB1=fma2(r1,w2[1],aB1);                        \
        aA2=fma2(q2,w2[2],aA2); aB2=fma2(r2,w2[2],aB2);                        \
        aA3=fma2(q3,w2[3],aA3); aB3=fma2(r3,w2[3],aB3);                        \
        aA0=fma2(q4,w2[4],aA0); aB0=fma2(r4,w2[4],aB0);                        \
        aA1=fma2(q5,w2[5],aA1); aB1=fma2(r5,w2[5],aB1);                        \
        aA2=fma2(q6,w2[6],aA2); aB2=fma2(r6,w2[6],aB2);                        \
        aA3=fma2(q7,w2[7],aA3); aB3=fma2(r7,w2[7],aB3);                        \
        lds2(q0,q1,sA + 64); lds2(r0,r1,sB + 64);                              \
        lds2(q2,q3,sA + 80); lds2(r2,r3,sB + 80);                              \
        lds2(q4,q5,sA + 96); lds2(r4,r5,sB + 96);                              \
        lds2(q6,q7,sA +112); lds2(r6,r7,sB +112);                              \
        aA0=fma2(q0,w2[ 8],aA0); aB0=fma2(r0,w2[ 8],aB0);                      \
        aA1=fma2(q1,w2[ 9],aA1); aB1=fma2(r1,w2[ 9],aB1);                      \
        aA2=fma2(q2,w2[10],aA2); aB2=fma2(r2,w2[10],aB2);                      \
        aA3=fma2(q3,w2[11],aA3); aB3=fma2(r3,w2[11],aB3);                      \
        aA0=fma2(q4,w2[12],aA0); aB0=fma2(r4,w2[12],aB0);                      \
        aA1=fma2(q5,w2[13],aA1); aB1=fma2(r5,w2[13],aB1);                      \
        aA2=fma2(q6,w2[14],aA2); aB2=fma2(r6,w2[14],aB2);                      \
        aA3=fma2(q7,w2[15],aA3); aB3=fma2(r7,w2[15],aB3);                      \
        ull sa = add2(add2(aA0,aA1), add2(aA2,aA3));                           \
        ull sb = add2(add2(aB0,aB1), add2(aB2,aB3));                           \
        float loA,hiA,loB,hiB;                                                 \
        unpack2(sa,loA,hiA); unpack2(sb,loB,hiB);                              \
        hA = fast_tanh(xuA + loA + hiA);                                       \
        hB = fast_tanh(xuB + loB + hiB);                                       \
        hbuf[wl][(PAR)^1][0][lane] = hA;                                       \
        hbuf[wl][(PAR)^1][1][lane] = hB;                                       \
    }

    for (int g = 0; g < SEQ / 4; g++) {
        int gn = (g + 1 < SEQ / 4) ? g + 1 : g;   // clamp: trailing prefetches discarded
        int4 tnA = __ldg(&xbA[gn]);
        int4 tnB = __ldg(&xbB[gn]);
        STEP(0, xpA0, xpB0, tA.z,  tB.z );        // s = 4g+0, prefetch s+2
        STEP(1, xpA1, xpB1, tA.w,  tB.w );        // s = 4g+1
        STEP(0, xpA0, xpB0, tnA.x, tnB.x);        // s = 4g+2
        STEP(1, xpA1, xpB1, tnA.y, tnB.y);        // s = 4g+3
        tA = tnA; tB = tnB;
    }
#undef STEP

    // Classifier head for both sequences (4 warp reductions).
    float vA0 = hA * __ldg(W_fc + lane);
    float vA1 = hA * __ldg(W_fc + HID + lane);
    float vB0 = hB * __ldg(W_fc + lane);
    float vB1 = hB * __ldg(W_fc + HID + lane);
#pragma unroll
    for (int o = 16; o > 0; o >>= 1) {
        vA0 += __shfl_xor_sync(0xffffffffu, vA0, o);
        vA1 += __shfl_xor_sync(0xffffffffu, vA1, o);
        vB0 += __shfl_xor_sync(0xffffffffu, vB0, o);
        vB1 += __shfl_xor_sync(0xffffffffu, vB1, o);
    }
    if (lane == 0) {
        float bf0 = __ldg(b_fc + 0), bf1 = __ldg(b_fc + 1);
        out[(base + 0) * NCLS + 0] = vA0 + bf0;
        out[(base + 0) * NCLS + 1] = vA1 + bf1;
        out[(base + 1) * NCLS + 0] = vB0 + bf0;
        out[(base + 1) * NCLS + 1] = vB1 + bf1;
    }
}

extern "C" void kernel_launch(void* const* d_in, const int* in_sizes, int n_in,
                              void* d_out, int out_size) {
    const int*   x    = (const int*)d_in[0];
    const float* emb  = (const float*)d_in[1];
    const float* W_ih = (const float*)d_in[2];
    const float* W_hh = (const float*)d_in[3];
    const float* b_ih = (const float*)d_in[4];
    const float* b_hh = (const float*)d_in[5];
    const float* W_fc = (const float*)d_in[6];
    const float* b_fc = (const float*)d_in[7];
    float* out = (float*)d_out;

    build_proj_kernel<<<(VOCAB + 7) / 8, 256>>>(emb, W_ih, b_ih, b_hh);
    rnn_step_kernel<<<BATCH / 8, 128>>>(x, W_hh, W_fc, b_fc, out);
}

// round 6
// speedup vs baseline: 1.1467x; 1.1467x over previous
#include <cuda_runtime.h>

#define VOCAB 10000
#define EMB   16
#define HID   32
#define NCLS  2
#define BATCH 4096
#define SEQ   512

typedef unsigned long long ull;

// Projected embedding table: proj[t][h] = sum_e emb[t][e]*W_ih[h][e] + b_ih[h] + b_hh[h]
__device__ float g_proj[VOCAB * HID];

__global__ void build_proj_kernel(const float* __restrict__ emb,
                                  const float* __restrict__ W_ih,
                                  const float* __restrict__ b_ih,
                                  const float* __restrict__ b_hh) {
    int t    = blockIdx.x * (blockDim.x >> 5) + (threadIdx.x >> 5);
    int lane = threadIdx.x & 31;
    if (t >= VOCAB) return;
    float acc = __ldg(b_ih + lane) + __ldg(b_hh + lane);
#pragma unroll
    for (int e = 0; e < EMB; e++) {
        acc = fmaf(__ldg(emb + t * EMB + e), __ldg(W_ih + lane * EMB + e), acc);
    }
    g_proj[t * HID + lane] = acc;
}

// tanh(x) = 1 - 2/(e^{2x}+1), branch-free via MUFU ex2/rcp. abs err ~1e-6.
__device__ __forceinline__ float fast_tanh(float x) {
    float e;
    asm("ex2.approx.f32 %0, %1;" : "=f"(e) : "f"(x * 2.8853900817779268f));
    float r;
    asm("rcp.approx.f32 %0, %1;" : "=f"(r) : "f"(e + 1.0f));
    return fmaf(-2.0f, r, 1.0f);
}

__device__ __forceinline__ ull pack2(float lo, float hi) {
    ull u;
    asm("mov.b64 %0, {%1, %2};" : "=l"(u) : "f"(lo), "f"(hi));
    return u;
}
__device__ __forceinline__ void unpack2(ull u, float& lo, float& hi) {
    asm("mov.b64 {%0, %1}, %2;" : "=f"(lo), "=f"(hi) : "l"(u));
}
__device__ __forceinline__ ull fma2(ull a, ull b, ull c) {
    asm("fma.rn.f32x2 %0, %1, %2, %3;" : "=l"(c) : "l"(a), "l"(b), "l"(c));
    return c;
}
__device__ __forceinline__ ull add2(ull a, ull b) {
    ull c;
    asm("add.rn.f32x2 %0, %1, %2;" : "=l"(c) : "l"(a), "l"(b));
    return c;
}
// 128-bit shared load -> two packed f32x2 operands (volatile: addresses repeat).
__device__ __forceinline__ void lds2(ull& a, ull& b, unsigned addr) {
    asm volatile("ld.shared.v2.u64 {%0, %1}, [%2];" : "=l"(a), "=l"(b) : "r"(addr));
}

// One warp per sequence; lane = hidden unit. 64-thread blocks, regs pinned so
// all 4096 warps are resident in ONE wave (28 warps/SM needs <=73 regs).
__global__ void __launch_bounds__(64, 14) rnn_step_kernel(
    const int* __restrict__ x,
    const float* __restrict__ W_hh,
    const float* __restrict__ W_fc,
    const float* __restrict__ b_fc,
    float* __restrict__ out) {

    int wl   = threadIdx.x >> 5;
    int lane = threadIdx.x & 31;
    int b    = blockIdx.x * 2 + wl;

    __shared__ __align__(16) float hbuf[2][2][HID];

    // W_hh row for this lane, packed into 16 f32x2 registers.
    ull w2[HID / 2];
#pragma unroll
    for (int j = 0; j < HID / 2; j++) {
        float2 wf = __ldg((const float2*)(W_hh + lane * HID) + j);
        w2[j] = pack2(wf.x, wf.y);
    }

    unsigned hb0 = (unsigned)__cvta_generic_to_shared(&hbuf[wl][0][0]);
    unsigned hb1 = (unsigned)__cvta_generic_to_shared(&hbuf[wl][1][0]);

    const int4* xb4 = (const int4*)(x + b * SEQ);

    hbuf[wl][0][lane] = 0.0f;
    float h = 0.0f;

    // Prime the 2-deep proj prefetch pipeline (tokens 0,1).
    int4 tc = __ldg(xb4);
    float xpA = __ldg(&g_proj[tc.x * HID + lane]);
    float xpB = __ldg(&g_proj[tc.y * HID + lane]);

#define STEP(PAR, XP, TOKPF)                                                   \
    {                                                                          \
        float xu = (XP);                                                       \
        (XP) = __ldg(&g_proj[(TOKPF) * HID + lane]); /* prefetch s+2 */        \
        __syncwarp();                                                          \
        unsigned src = (PAR) ? hb1 : hb0;                                      \
        ull p0, p1, p2, p3, p4, p5, p6, p7;                                    \
        ull a0 = pack2(xu, 0.0f);  /* xp seeds the accumulator tree */         \
        ull a1 = 0, a2 = 0, a3 = 0;                                            \
        lds2(p0, p1, src);                                                     \
        lds2(p2, p3, src + 16);                                                \
        lds2(p4, p5, src + 32);                                                \
        lds2(p6, p7, src + 48);                                                \
        a0 = fma2(p0, w2[0], a0); a1 = fma2(p1, w2[1], a1);                    \
        a2 = fma2(p2, w2[2], a2); a3 = fma2(p3, w2[3], a3);                    \
        a0 = fma2(p4, w2[4], a0); a1 = fma2(p5, w2[5], a1);                    \
        a2 = fma2(p6, w2[6], a2); a3 = fma2(p7, w2[7], a3);                    \
        lds2(p0, p1, src + 64);                                                \
        lds2(p2, p3, src + 80);                                                \
        lds2(p4, p5, src + 96);                                                \
        lds2(p6, p7, src + 112);                                               \
        a0 = fma2(p0, w2[8],  a0); a1 = fma2(p1, w2[9],  a1);                  \
        a2 = fma2(p2, w2[10], a2); a3 = fma2(p3, w2[11], a3);                  \
        a0 = fma2(p4, w2[12], a0); a1 = fma2(p5, w2[13], a1);                  \
        a2 = fma2(p6, w2[14], a2); a3 = fma2(p7, w2[15], a3);                  \
        ull ss = add2(add2(a0, a1), add2(a2, a3));                             \
        float lo, hi;                                                          \
        unpack2(ss, lo, hi);                                                   \
        h = fast_tanh(lo + hi);                                                \
        hbuf[wl][(PAR) ^ 1][lane] = h;                                         \
    }

    for (int g = 0; g < SEQ / 4; g++) {
        int gn = (g + 1 < SEQ / 4) ? g + 1 : g;   // clamp: trailing prefetches discarded
        int4 tn = __ldg(&xb4[gn]);                // one uniform LDG.128 per 4 steps
        STEP(0, xpA, tc.z);   // s = 4g+0, prefetch s+2
        STEP(1, xpB, tc.w);   // s = 4g+1
        STEP(0, xpA, tn.x);   // s = 4g+2
        STEP(1, xpB, tn.y);   // s = 4g+3
        tc = tn;
    }
#undef STEP

    // Classifier head: two warp reductions.
    float v0 = h * __ldg(W_fc + lane);
    float v1 = h * __ldg(W_fc + HID + lane);
#pragma unroll
    for (int o = 16; o > 0; o >>= 1) {
        v0 += __shfl_xor_sync(0xffffffffu, v0, o);
        v1 += __shfl_xor_sync(0xffffffffu, v1, o);
    }
    if (lane == 0) {
        out[b * NCLS + 0] = v0 + __ldg(b_fc + 0);
        out[b * NCLS + 1] = v1 + __ldg(b_fc + 1);
    }
}

extern "C" void kernel_launch(void* const* d_in, const int* in_sizes, int n_in,
                              void* d_out, int out_size) {
    const int*   x    = (const int*)d_in[0];
    const float* emb  = (const float*)d_in[1];
    const float* W_ih = (const float*)d_in[2];
    const float* W_hh = (const float*)d_in[3];
    const float* b_ih = (const float*)d_in[4];
    const float* b_hh = (const float*)d_in[5];
    const float* W_fc = (const float*)d_in[6];
    const float* b_fc = (const float*)d_in[7];
    float* out = (float*)d_out;

    build_proj_kernel<<<(VOCAB + 7) / 8, 256>>>(emb, W_ih, b_ih, b_hh);
    rnn_step_kernel<<<BATCH / 2, 64>>>(x, W_hh, W_fc, b_fc, out);
}

// round 8
// speedup vs baseline: 1.2368x; 1.0786x over previous
#include <cuda_runtime.h>

#define VOCAB 10000
#define EMB   16
#define HID   32
#define NCLS  2
#define BATCH 4096
#define SEQ   512

typedef unsigned long long ull;

#define TANH_C 2.885390081777927f   // 2*log2(e): tanh(x) = 1 - 2/(exp2(x*C)+1)

// Prescaled projected embedding: g_projC[t][h] = C * (sum_e emb[t][e]*W_ih[h][e] + b_ih[h] + b_hh[h])
__device__ float g_projC[VOCAB * HID];

__global__ void build_proj_kernel(const float* __restrict__ emb,
                                  const float* __restrict__ W_ih,
                                  const float* __restrict__ b_ih,
                                  const float* __restrict__ b_hh) {
    int t    = blockIdx.x * (blockDim.x >> 5) + (threadIdx.x >> 5);
    int lane = threadIdx.x & 31;
    if (t >= VOCAB) return;
    float acc = __ldg(b_ih + lane) + __ldg(b_hh + lane);
#pragma unroll
    for (int e = 0; e < EMB; e++) {
        acc = fmaf(__ldg(emb + t * EMB + e), __ldg(W_ih + lane * EMB + e), acc);
    }
    g_projC[t * HID + lane] = acc * TANH_C;
}

__device__ __forceinline__ ull pack2(float lo, float hi) {
    ull u;
    asm("mov.b64 %0, {%1, %2};" : "=l"(u) : "f"(lo), "f"(hi));
    return u;
}
__device__ __forceinline__ void unpack2(ull u, float& lo, float& hi) {
    asm("mov.b64 {%0, %1}, %2;" : "=f"(lo), "=f"(hi) : "l"(u));
}
__device__ __forceinline__ ull fma2(ull a, ull b, ull c) {
    asm("fma.rn.f32x2 %0, %1, %2, %3;" : "=l"(c) : "l"(a), "l"(b), "l"(c));
    return c;
}
// 128-bit shared load -> two packed f32x2 operands (volatile: addresses repeat).
__device__ __forceinline__ void lds2(ull& a, ull& b, unsigned addr) {
    asm volatile("ld.shared.v2.u64 {%0, %1}, [%2];" : "=l"(a), "=l"(b) : "r"(addr));
}

// Split-K layout: lane = (q = lane>>2, c = lane&3).
//  - owns h-chunk k in [8c, 8c+8)  (32B/lane -> 1KB delivered/step, was 4KB)
//  - computes partials for outputs j in {q, q+8, q+16, q+24}
//  - 4x4 transpose-reduce (3 shfl + 3 fadd) lands output j = q+8c on this lane.
__global__ void __launch_bounds__(64, 14) rnn_step_kernel(
    const int* __restrict__ x,
    const float* __restrict__ W_hh,
    const float* __restrict__ W_fc,
    const float* __restrict__ b_fc,
    float* __restrict__ out) {

    int wl   = threadIdx.x >> 5;
    int lane = threadIdx.x & 31;
    int q    = lane >> 2;
    int c    = lane & 3;
    int p    = q + 8 * c;            // the output index this lane finalizes
    int b    = blockIdx.x * 2 + wl;

    __shared__ __align__(16) float hbuf[2][2][HID];

    // W_hh[j][k] for j = q+8*jj, k = 8c+2i.. : 16 packed pairs.
    ull w2[16];
#pragma unroll
    for (int jj = 0; jj < 4; jj++) {
        const float2* wr = (const float2*)(W_hh + (q + 8 * jj) * HID + 8 * c);
#pragma unroll
        for (int i = 0; i < 4; i++) {
            float2 wf = __ldg(wr + i);
            w2[jj * 4 + i] = pack2(wf.x, wf.y);
        }
    }

    unsigned hb0 = (unsigned)__cvta_generic_to_shared(&hbuf[wl][0][0]) + c * 32;
    unsigned hb1 = (unsigned)__cvta_generic_to_shared(&hbuf[wl][1][0]) + c * 32;

    const int4* xb4 = (const int4*)(x + b * SEQ);

    hbuf[wl][0][p] = 0.0f;
    float h = 0.0f;

    bool s0sel = (c & 1);
    bool s1sel = (c & 2);

    // Prime the 2-deep proj prefetch pipeline (tokens 0,1).
    int4 tc = __ldg(xb4);
    float xpA = __ldg(&g_projC[tc.x * HID + p]);
    float xpB = __ldg(&g_projC[tc.y * HID + p]);

#define STEP(PAR, XP, TOKPF)                                                   \
    {                                                                          \
        float xuC = (XP);                                                      \
        (XP) = __ldg(&g_projC[(TOKPF) * HID + p]); /* prefetch s+2 */          \
        __syncwarp();                                                          \
        unsigned src = (PAR) ? hb1 : hb0;                                      \
        ull hp0, hp1, hp2, hp3;                                                \
        lds2(hp0, hp1, src);                                                   \
        lds2(hp2, hp3, src + 16);                                              \
        ull a0 = 0, a1 = 0, a2 = 0, a3 = 0;                                    \
        a0 = fma2(hp0, w2[0],  a0); a1 = fma2(hp0, w2[4],  a1);                \
        a2 = fma2(hp0, w2[8],  a2); a3 = fma2(hp0, w2[12], a3);                \
        a0 = fma2(hp1, w2[1],  a0); a1 = fma2(hp1, w2[5],  a1);                \
        a2 = fma2(hp1, w2[9],  a2); a3 = fma2(hp1, w2[13], a3);                \
        a0 = fma2(hp2, w2[2],  a0); a1 = fma2(hp2, w2[6],  a1);                \
        a2 = fma2(hp2, w2[10], a2); a3 = fma2(hp2, w2[14], a3);                \
        a0 = fma2(hp3, w2[3],  a0); a1 = fma2(hp3, w2[7],  a1);                \
        a2 = fma2(hp3, w2[11], a2); a3 = fma2(hp3, w2[15], a3);                \
        float l0, h0, l1, h1, l2, h2, l3, h3;                                  \
        unpack2(a0, l0, h0); unpack2(a1, l1, h1);                              \
        unpack2(a2, l2, h2); unpack2(a3, l3, h3);                              \
        float s0 = l0 + h0, s1 = l1 + h1, s2 = l2 + h2, s3 = l3 + h3;          \
        /* 4x4 transpose-reduce across the c-group */                          \
        float k0 = s0sel ? s1 : s0, d0 = s0sel ? s0 : s1;                      \
        float k1 = s0sel ? s3 : s2, d1 = s0sel ? s2 : s3;                      \
        float u0 = k0 + __shfl_xor_sync(0xffffffffu, d0, 1);                   \
        float u1 = k1 + __shfl_xor_sync(0xffffffffu, d1, 1);                   \
        float kv = s1sel ? u1 : u0, dv = s1sel ? u0 : u1;                      \
        float v  = kv + __shfl_xor_sync(0xffffffffu, dv, 2);                   \
        float e;                                                               \
        asm("ex2.approx.f32 %0, %1;" : "=f"(e) : "f"(fmaf(v, TANH_C, xuC)));   \
        float r;                                                               \
        asm("rcp.approx.f32 %0, %1;" : "=f"(r) : "f"(e + 1.0f));               \
        h = fmaf(-2.0f, r, 1.0f);                                              \
        hbuf[wl][(PAR) ^ 1][p] = h;                                            \
    }

    for (int g = 0; g < SEQ / 4; g++) {
        int gn = (g + 1 < SEQ / 4) ? g + 1 : g;   // clamp: trailing prefetches discarded
        int4 tn = __ldg(&xb4[gn]);                // one uniform LDG.128 per 4 steps
        STEP(0, xpA, tc.z);   // s = 4g+0, prefetch s+2
        STEP(1, xpB, tc.w);   // s = 4g+1
        STEP(0, xpA, tn.x);   // s = 4g+2
        STEP(1, xpB, tn.y);   // s = 4g+3
        tc = tn;
    }
#undef STEP

    // Classifier head: lane holds h_final[p]; two full-warp reductions.
    float v0 = h * __ldg(W_fc + p);
    float v1 = h * __ldg(W_fc + HID + p);
#pragma unroll
    for (int o = 16; o > 0; o >>= 1) {
        v0 += __shfl_xor_sync(0xffffffffu, v0, o);
        v1 += __shfl_xor_sync(0xffffffffu, v1, o);
    }
    if (lane == 0) {
        out[b * NCLS + 0] = v0 + __ldg(b_fc + 0);
        out[b * NCLS + 1] = v1 + __ldg(b_fc + 1);
    }
}

extern "C" void kernel_launch(void* const* d_in, const int* in_sizes, int n_in,
                              void* d_out, int out_size) {
    const int*   x    = (const int*)d_in[0];
    const float* emb  = (const float*)d_in[1];
    const float* W_ih = (const float*)d_in[2];
    const float* W_hh = (const float*)d_in[3];
    const float* b_ih = (const float*)d_in[4];
    const float* b_hh = (const float*)d_in[5];
    const float* W_fc = (const float*)d_in[6];
    const float* b_fc = (const float*)d_in[7];
    float* out = (float*)d_out;

    build_proj_kernel<<<(VOCAB + 7) / 8, 256>>>(emb, W_ih, b_ih, b_hh);
    rnn_step_kernel<<<BATCH / 2, 64>>>(x, W_hh, W_fc, b_fc, out);
}

// round 9
// speedup vs baseline: 1.2588x; 1.0178x over previous
#include <cuda_runtime.h>

#define VOCAB 10000
#define EMB   16
#define HID   32
#define NCLS  2
#define BATCH 4096
#define SEQ   512

typedef unsigned long long ull;

#define TANH_C 2.885390081777927f   // 2*log2(e): tanh(x) = 1 - 2/(exp2(x*C)+1)

// Prescaled projected embedding: g_projC[t][h] = C * (sum_e emb[t][e]*W_ih[h][e] + b_ih[h] + b_hh[h])
__device__ float g_projC[VOCAB * HID];

__global__ void build_proj_kernel(const float* __restrict__ emb,
                                  const float* __restrict__ W_ih,
                                  const float* __restrict__ b_ih,
                                  const float* __restrict__ b_hh) {
    int t    = blockIdx.x * (blockDim.x >> 5) + (threadIdx.x >> 5);
    int lane = threadIdx.x & 31;
    if (t >= VOCAB) return;
    float acc = __ldg(b_ih + lane) + __ldg(b_hh + lane);
#pragma unroll
    for (int e = 0; e < EMB; e++) {
        acc = fmaf(__ldg(emb + t * EMB + e), __ldg(W_ih + lane * EMB + e), acc);
    }
    g_projC[t * HID + lane] = acc * TANH_C;
}

__device__ __forceinline__ ull pack2(float lo, float hi) {
    ull u;
    asm("mov.b64 %0, {%1, %2};" : "=l"(u) : "f"(lo), "f"(hi));
    return u;
}
__device__ __forceinline__ void unpack2(ull u, float& lo, float& hi) {
    asm("mov.b64 {%0, %1}, %2;" : "=f"(lo), "=f"(hi) : "l"(u));
}
__device__ __forceinline__ ull fma2(ull a, ull b, ull c) {
    asm("fma.rn.f32x2 %0, %1, %2, %3;" : "=l"(c) : "l"(a), "l"(b), "l"(c));
    return c;
}
// 128-bit shared load -> two packed f32x2 operands (volatile: addresses repeat).
__device__ __forceinline__ void lds2(ull& a, ull& b, unsigned addr) {
    asm volatile("ld.shared.v2.u64 {%0, %1}, [%2];" : "=l"(a), "=l"(b) : "r"(addr));
}

// Split-K layout: lane = (q = lane>>2, c = lane&3).
//  - owns h-chunk k in [8c, 8c+8)  (2 LDS.128/step)
//  - accumulator i holds the partial for output row  q + 8*(c^i)   <-- permuted!
//  - pure butterfly (3 shfl + 3 fadd, NO selects) lands output p = q+8c here.
__global__ void __launch_bounds__(64, 14) rnn_step_kernel(
    const int* __restrict__ x,
    const float* __restrict__ W_hh,
    const float* __restrict__ W_fc,
    const float* __restrict__ b_fc,
    float* __restrict__ out) {

    int wl   = threadIdx.x >> 5;
    int lane = threadIdx.x & 31;
    int q    = lane >> 2;
    int c    = lane & 3;
    int p    = q + 8 * c;            // the output index this lane finalizes
    int b    = blockIdx.x * 2 + wl;

    __shared__ __align__(16) float hbuf[2][2][HID];

    // w2[i*4 + t] pairs with accumulator i: W_hh[q + 8*(c^i)][8c + 2t .. +2).
    ull w2[16];
#pragma unroll
    for (int i = 0; i < 4; i++) {
        const float2* wr = (const float2*)(W_hh + (q + 8 * (c ^ i)) * HID + 8 * c);
#pragma unroll
        for (int t = 0; t < 4; t++) {
            float2 wf = __ldg(wr + t);
            w2[i * 4 + t] = pack2(wf.x, wf.y);
        }
    }

    unsigned hb0 = (unsigned)__cvta_generic_to_shared(&hbuf[wl][0][0]) + c * 32;
    unsigned hb1 = (unsigned)__cvta_generic_to_shared(&hbuf[wl][1][0]) + c * 32;

    const int4* xb4 = (const int4*)(x + b * SEQ);

    hbuf[wl][0][p] = 0.0f;
    float h = 0.0f;

    // Prime the 2-deep proj prefetch pipeline (tokens 0,1).
    int4 tc = __ldg(xb4);
    float xpA = __ldg(&g_projC[tc.x * HID + p]);
    float xpB = __ldg(&g_projC[tc.y * HID + p]);

#define STEP(PAR, XP, TOKPF)                                                   \
    {                                                                          \
        float xuC = (XP);                                                      \
        (XP) = __ldg(&g_projC[(TOKPF) * HID + p]); /* prefetch s+2 */          \
        __syncwarp();                                                          \
        unsigned src = (PAR) ? hb1 : hb0;                                      \
        ull hp0, hp1, hp2, hp3;                                                \
        lds2(hp0, hp1, src);                                                   \
        lds2(hp2, hp3, src + 16);                                              \
        ull a0 = 0, a1 = 0, a2 = 0, a3 = 0;                                    \
        a0 = fma2(hp0, w2[0],  a0); a1 = fma2(hp0, w2[4],  a1);                \
        a2 = fma2(hp0, w2[8],  a2); a3 = fma2(hp0, w2[12], a3);                \
        a0 = fma2(hp1, w2[1],  a0); a1 = fma2(hp1, w2[5],  a1);                \
        a2 = fma2(hp1, w2[9],  a2); a3 = fma2(hp1, w2[13], a3);                \
        a0 = fma2(hp2, w2[2],  a0); a1 = fma2(hp2, w2[6],  a1);                \
        a2 = fma2(hp2, w2[10], a2); a3 = fma2(hp2, w2[14], a3);                \
        a0 = fma2(hp3, w2[3],  a0); a1 = fma2(hp3, w2[7],  a1);                \
        a2 = fma2(hp3, w2[11], a2); a3 = fma2(hp3, w2[15], a3);                \
        float l0, h0, l1, h1, l2, h2, l3, h3;                                  \
        unpack2(a0, l0, h0); unpack2(a1, l1, h1);                              \
        unpack2(a2, l2, h2); unpack2(a3, l3, h3);                              \
        float s0 = l0 + h0, s1 = l1 + h1, s2 = l2 + h2, s3 = l3 + h3;          \
        /* permuted butterfly: partials for output p converge on this lane */  \
        float u0 = s0 + __shfl_xor_sync(0xffffffffu, s1, 1);                   \
        float u1 = s2 + __shfl_xor_sync(0xffffffffu, s3, 1);                   \
        float v  = u0 + __shfl_xor_sync(0xffffffffu, u1, 2);                   \
        float e;                                                               \
        asm("ex2.approx.f32 %0, %1;" : "=f"(e) : "f"(fmaf(v, TANH_C, xuC)));   \
        float r;                                                               \
        asm("rcp.approx.f32 %0, %1;" : "=f"(r) : "f"(e + 1.0f));               \
        h = fmaf(-2.0f, r, 1.0f);                                              \
        hbuf[wl][(PAR) ^ 1][p] = h;                                            \
    }

    for (int g = 0; g < SEQ / 4; g++) {
        int gn = (g + 1 < SEQ / 4) ? g + 1 : g;   // clamp: trailing prefetches discarded
        int4 tn = __ldg(&xb4[gn]);                // one uniform LDG.128 per 4 steps
        STEP(0, xpA, tc.z);   // s = 4g+0, prefetch s+2
        STEP(1, xpB, tc.w);   // s = 4g+1
        STEP(0, xpA, tn.x);   // s = 4g+2
        STEP(1, xpB, tn.y);   // s = 4g+3
        tc = tn;
    }
#undef STEP

    // Classifier head: lane holds h_final[p]; two full-warp reductions.
    float v0 = h * __ldg(W_fc + p);
    float v1 = h * __ldg(W_fc + HID + p);
#pragma unroll
    for (int o = 16; o > 0; o >>= 1) {
        v0 += __shfl_xor_sync(0xffffffffu, v0, o);
        v1 += __shfl_xor_sync(0xffffffffu, v1, o);
    }
    if (lane == 0) {
        out[b * NCLS + 0] = v0 + __ldg(b_fc + 0);
        out[b * NCLS + 1] = v1 + __ldg(b_fc + 1);
    }
}

extern "C" void kernel_launch(void* const* d_in, const int* in_sizes, int n_in,
                              void* d_out, int out_size) {
    const int*   x    = (const int*)d_in[0];
    const float* emb  = (const float*)d_in[1];
    const float* W_ih = (const float*)d_in[2];
    const float* W_hh = (const float*)d_in[3];
    const float* b_ih = (const float*)d_in[4];
    const float* b_hh = (const float*)d_in[5];
    const float* W_fc = (const float*)d_in[6];
    const float* b_fc = (const float*)d_in[7];
    float* out = (float*)d_out;

    build_proj_kernel<<<(VOCAB + 7) / 8, 256>>>(emb, W_ih, b_ih, b_hh);
    rnn_step_kernel<<<BATCH / 2, 64>>>(x, W_hh, W_fc, b_fc, out);
}